// round 11
// baseline (speedup 1.0000x reference)
#include <cuda_runtime.h>

#define NJ   32
#define TPB  128
#define EPB  (TPB / 2)     // 64 elements per block, 2 threads each
#define OUTC 94

// ---- dynamic smem float offsets ----
#define S_OUT   0                       // EPB*OUTC = 6016 floats (also cfg-stage scratch)
#define S_BASE  (EPB * OUTC)            // 6016  (EPB x 8, padded)
#define S_TGT   (S_BASE + EPB * 8)      // 6528  (4 x 8, padded)
#define S_DB    (S_TGT + 32)            // 6560  (8)
#define S_REC   (S_DB + 8)              // 6568  (32 x 16 joint records)
#define S_TOTAL (S_REC + 512)           // 7080 floats = 28320 B

#define CFG_PAD 36                      // padded cfg row stride in staging scratch

struct Q { float x, y, z, w; };
struct V { float x, y, z; };

__device__ __forceinline__ V vcross(V a, V b) {
    return {a.y * b.z - a.z * b.y,
            a.z * b.x - a.x * b.z,
            a.x * b.y - a.y * b.x};
}

__device__ __forceinline__ V qrot(Q q, V t) {
    V v{q.x, q.y, q.z};
    V u = vcross(v, t);
    u.x = fmaf(q.w, t.x, u.x);
    u.y = fmaf(q.w, t.y, u.y);
    u.z = fmaf(q.w, t.z, u.z);
    V c = vcross(v, u);
    return {fmaf(2.0f, c.x, t.x), fmaf(2.0f, c.y, t.y), fmaf(2.0f, c.z, t.z)};
}

__device__ __forceinline__ Q qmul(Q a, Q b) {
    Q r;
    r.w = a.w * b.w - a.x * b.x - a.y * b.y - a.z * b.z;
    r.x = a.w * b.x + b.w * a.x + a.y * b.z - a.z * b.y;
    r.y = a.w * b.y + b.w * a.y + a.z * b.x - a.x * b.z;
    r.z = a.w * b.z + b.w * a.z + a.x * b.y - a.y * b.x;
    return r;
}

// (t1,q1) <- (t1,q1) o (t2,q2)
__device__ __forceinline__ void se3_acc(V& t1, Q& q1, V t2, Q q2) {
    V r = qrot(q1, t2);
    t1.x += r.x; t1.y += r.y; t1.z += r.z;
    q1 = qmul(q1, q2);
}

// out = (t1,q1) o (t2,q2)
__device__ __forceinline__ void se3_comp(V t1, Q q1, V t2, Q q2, V& to, Q& qo) {
    V r = qrot(q1, t2);
    to.x = t1.x + r.x; to.y = t1.y + r.y; to.z = t1.z + r.z;
    qo = qmul(q1, q2);
}

// atan2(y,x), y >= 0, x >= 0, not both zero
__device__ __forceinline__ float atan2pos(float y, float x) {
    float mn = fminf(y, x), mx = fmaxf(y, x);
    float r  = __fdividef(mn, mx);
    float r2 = r * r;
    float p = fmaf(r2, -0.0117212f,  0.05265332f);
    p = fmaf(r2, p, -0.11643287f);
    p = fmaf(r2, p,  0.19354346f);
    p = fmaf(r2, p, -0.33262347f);
    p = fmaf(r2, p,  0.99997726f);
    float th = r * p;
    return (y > x) ? (1.57079632679489662f - th) : th;
}

// se3_log for unit quaternion (trig-free tail)
__device__ __forceinline__ void se3_log(V t, Q q, V& rho, V& phi) {
    float sgn = (q.w < 0.0f) ? -1.0f : 1.0f;
    float qx = q.x * sgn, qy = q.y * sgn, qz = q.z * sgn, qw = q.w * sgn;
    float nv2 = qx * qx + qy * qy + qz * qz;
    float nv  = sqrtf(fmaxf(nv2, 1e-14f));
    float angle = 2.0f * atan2pos(nv, qw);
    float wsafe = (fabsf(qw) > 1e-8f) ? qw : 1.0f;
    float scale = (nv < 1e-6f) ? __fdividef(2.0f, wsafe) : __fdividef(angle, nv);
    phi = {qx * scale, qy * scale, qz * scale};

    float th2 = angle * angle;
    float abig = __fdividef(1.0f - 0.5f * scale * qw, th2);
    float a = (angle < 1e-4f) ? (1.0f / 12.0f + th2 * (1.0f / 720.0f)) : abig;

    V pt  = vcross(phi, t);
    V ppt = vcross(phi, pt);
    rho = {t.x - 0.5f * pt.x + a * ppt.x,
           t.y - 0.5f * pt.y + a * ppt.y,
           t.z - 0.5f * pt.z + a * ppt.z};
}

// log( inv(target) o actual ); target padded to 8 floats: [t(3),pad | q(4)]
__device__ __forceinline__ void pose_err_log(const float* tp, V at, Q aq,
                                             V& rho, V& phi) {
    float4 a = *(const float4*)tp;
    float4 b = *(const float4*)(tp + 4);
    Q qi{-b.x, -b.y, -b.z, b.w};
    V d{at.x - a.x, at.y - a.y, at.z - a.z};
    V pe = qrot(qi, d);
    Q qe = qmul(qi, aq);
    se3_log(pe, qe, rho, phi);
}

// one leaf: M = ch*oq + sh*P, T = ot; also writes limit/rest residuals
__device__ __forceinline__ void leaf(const float4* REC, int j, float thj,
                                     float* row, V& T, Q& M) {
    const float4* R = REC + j * 4;
    float4 a0 = R[0];     // ot, rest
    float4 a1 = R[1];     // oq
    float4 a2 = R[2];     // P
    float4 a3 = R[3];     // up, lo
    float lim = fmaxf(thj - a3.x, 0.0f) + fminf(thj - a3.y, 0.0f);
    row[24 + j] = lim * 10.0f;
    row[56 + j] = (thj - a0.w) * 0.1f;

    float sh, ch;
    __sincosf(0.5f * thj, &sh, &ch);
    M.x = fmaf(sh, a2.x, ch * a1.x);
    M.y = fmaf(sh, a2.y, ch * a1.y);
    M.z = fmaf(sh, a2.z, ch * a1.z);
    M.w = fmaf(sh, a2.w, ch * a1.w);
    T.x = a0.x; T.y = a0.y; T.z = a0.z;
}

// product of X_{j0}..X_{j0+7}: interleaved leaf-build + compose (low reg pressure)
__device__ __forceinline__ void prod8(const float4* REC, int j0, const float* th8,
                                      float* row, V& St, Q& Sq) {
    V ta, tb; Q qa, qb;

    // A = X0 o X1
    leaf(REC, j0 + 0, th8[0], row, St, Sq);
    leaf(REC, j0 + 1, th8[1], row, ta, qa);
    se3_acc(St, Sq, ta, qa);
    // B = X2 o X3 ; A = A o B
    leaf(REC, j0 + 2, th8[2], row, ta, qa);
    leaf(REC, j0 + 3, th8[3], row, tb, qb);
    se3_acc(ta, qa, tb, qb);
    se3_acc(St, Sq, ta, qa);
    // C = X4 o X5
    V tc; Q qc;
    leaf(REC, j0 + 4, th8[4], row, tc, qc);
    leaf(REC, j0 + 5, th8[5], row, ta, qa);
    se3_acc(tc, qc, ta, qa);
    // D = X6 o X7 ; C = C o D ; S = A o C
    leaf(REC, j0 + 6, th8[6], row, ta, qa);
    leaf(REC, j0 + 7, th8[7], row, tb, qb);
    se3_acc(ta, qa, tb, qb);
    se3_acc(tc, qc, ta, qa);
    se3_acc(St, Sq, tc, qc);
}

__global__ void __launch_bounds__(TPB, 5)
ik_residual_kernel(const float* __restrict__ cfg,
                   const float* __restrict__ base,
                   const float* __restrict__ tgt,
                   const float* __restrict__ dbase,
                   const float* __restrict__ rest,
                   const float* __restrict__ joff,
                   const float* __restrict__ jaxis,
                   const float* __restrict__ jlo,
                   const float* __restrict__ jup,
                   float* __restrict__ out) {
    extern __shared__ __align__(16) float s[];

    const int t    = threadIdx.x;
    const int elem = t >> 1;        // 0..63
    const int seg  = t & 1;         // 0 -> joints 0-15, 1 -> joints 16-31
    const int e0   = blockIdx.x * EPB;

    // ---- stage: base (padded 8), cfg tile (-> S_OUT scratch), records, targets ----
    {
        const float* gb = base + (size_t)e0 * 7;
        #pragma unroll
        for (int i = t; i < EPB * 7; i += TPB) {
            int r = i / 7, c = i - r * 7;
            s[S_BASE + r * 8 + c] = gb[i];
        }

        const float4* gc = (const float4*)(cfg + (size_t)e0 * NJ);
        #pragma unroll
        for (int f = t; f < EPB * (NJ / 4); f += TPB) {
            int r = f >> 3;
            int c = f & 7;
            *(float4*)(s + S_OUT + r * CFG_PAD + c * 4) = __ldg(gc + f);
        }

        if (t < 32) {
            float otx = __ldg(joff + t * 7 + 0), oty = __ldg(joff + t * 7 + 1);
            float otz = __ldg(joff + t * 7 + 2);
            float ox = __ldg(joff + t * 7 + 3), oy = __ldg(joff + t * 7 + 4);
            float oz = __ldg(joff + t * 7 + 5), ow = __ldg(joff + t * 7 + 6);
            float ax = __ldg(jaxis + t * 3 + 0), ay = __ldg(jaxis + t * 3 + 1);
            float az = __ldg(jaxis + t * 3 + 2);
            float4* R = (float4*)(s + S_REC) + t * 4;
            R[0] = make_float4(otx, oty, otz, __ldg(rest + t));
            R[1] = make_float4(ox, oy, oz, ow);
            R[2] = make_float4(ow * ax + oy * az - oz * ay,
                               ow * ay + oz * ax - ox * az,
                               ow * az + ox * ay - oy * ax,
                               -(ox * ax + oy * ay + oz * az));
            R[3] = make_float4(__ldg(jup + t), __ldg(jlo + t), 0.0f, 0.0f);
        }
        if (t < 5) {
            const float* src = (t < 4) ? (tgt + t * 7) : dbase;
            float* dst = s + ((t < 4) ? (S_TGT + t * 8) : S_DB);
            dst[0] = __ldg(src + 0); dst[1] = __ldg(src + 1);
            dst[2] = __ldg(src + 2); dst[3] = 0.0f;
            dst[4] = __ldg(src + 3); dst[5] = __ldg(src + 4);
            dst[6] = __ldg(src + 5); dst[7] = __ldg(src + 6);
        }
    }
    __syncthreads();

    // own half of cfg row + base pose
    float th[16];
    {
        const float4* cr = (const float4*)(s + S_OUT + elem * CFG_PAD + seg * 16);
        #pragma unroll
        for (int i = 0; i < 4; i++) {
            float4 v = cr[i];
            th[4*i+0] = v.x; th[4*i+1] = v.y; th[4*i+2] = v.z; th[4*i+3] = v.w;
        }
    }
    float bp[7];
    {
        float4 b1 = *(const float4*)(s + S_BASE + elem * 8);
        float4 b2 = *(const float4*)(s + S_BASE + elem * 8 + 4);
        bp[0] = b1.x; bp[1] = b1.y; bp[2] = b1.z; bp[3] = b1.w;
        bp[4] = b2.x; bp[5] = b2.y; bp[6] = b2.z;
    }
    __syncthreads();   // cfg scratch becomes output staging

    float* row = s + S_OUT + elem * OUTC;
    const float4* REC = (const float4*)(s + S_REC);
    const int j0 = seg * 16;

    // ---- two 8-joint products + 16-joint product ----
    V S1t, S2t, Et; Q S1q, S2q, Eq;
    prod8(REC, j0,     th,     row, S1t, S1q);
    prod8(REC, j0 + 8, th + 8, row, S2t, S2q);
    se3_comp(S1t, S1q, S2t, S2q, Et, Eq);      // E = 16-joint product

    // ---- G = base o E (lane0 of pair: T16) ----
    V bt{bp[0], bp[1], bp[2]};
    Q bq{bp[3], bp[4], bp[5], bp[6]};
    V Gt; Q Gq;
    se3_comp(bt, bq, Et, Eq, Gt, Gq);

    // broadcast lane0's G (=T16) within the pair
    V Lt; Q Lq;
    Lt.x = __shfl_sync(0xffffffffu, Gt.x, 0, 2);
    Lt.y = __shfl_sync(0xffffffffu, Gt.y, 0, 2);
    Lt.z = __shfl_sync(0xffffffffu, Gt.z, 0, 2);
    Lq.x = __shfl_sync(0xffffffffu, Gq.x, 0, 2);
    Lq.y = __shfl_sync(0xffffffffu, Gq.y, 0, 2);
    Lq.z = __shfl_sync(0xffffffffu, Gq.z, 0, 2);
    Lq.w = __shfl_sync(0xffffffffu, Gq.w, 0, 2);

    // prefix select: seg0 -> base, seg1 -> T16
    V Pt; Q Pq;
    Pt.x = seg ? Lt.x : bt.x;  Pt.y = seg ? Lt.y : bt.y;  Pt.z = seg ? Lt.z : bt.z;
    Pq.x = seg ? Lq.x : bq.x;  Pq.y = seg ? Lq.y : bq.y;
    Pq.z = seg ? Lq.z : bq.z;  Pq.w = seg ? Lq.w : bq.w;

    // U1 = P o S1 (T8 / T24), U2 = P o E (T16 / T32) -- independent
    V U1t, U2t; Q U1q, U2q;
    se3_comp(Pt, Pq, S1t, S1q, U1t, U1q);
    se3_comp(Pt, Pq, Et,  Eq,  U2t, U2q);

    // ---- pose residuals (2 per thread) ----
    {
        V rho, phi;
        int k = seg * 2;
        pose_err_log(s + S_TGT + k * 8, U1t, U1q, rho, phi);
        *(float2*)(row + k * 6 + 0) = make_float2(rho.x, rho.y);
        *(float2*)(row + k * 6 + 2) = make_float2(rho.z, 0.5f * phi.x);
        *(float2*)(row + k * 6 + 4) = make_float2(0.5f * phi.y, 0.5f * phi.z);

        k = seg * 2 + 1;
        pose_err_log(s + S_TGT + k * 8, U2t, U2q, rho, phi);
        *(float2*)(row + k * 6 + 0) = make_float2(rho.x, rho.y);
        *(float2*)(row + k * 6 + 2) = make_float2(rho.z, 0.5f * phi.x);
        *(float2*)(row + k * 6 + 4) = make_float2(0.5f * phi.y, 0.5f * phi.z);
    }

    // ---- base residuals: all 4 warps, lanes 0-15, one element each ----
    {
        const int lane = t & 31;
        const int w    = t >> 5;
        if (lane < 16) {
            const int el = w * 16 + lane;   // 0..63
            float4 b1 = *(const float4*)(s + S_BASE + el * 8);
            float4 b2 = *(const float4*)(s + S_BASE + el * 8 + 4);
            V rho, phi;
            pose_err_log(s + S_DB, V{b1.x, b1.y, b1.z},
                         Q{b1.w, b2.x, b2.y, b2.z}, rho, phi);
            float* r2 = s + S_OUT + el * OUTC;
            *(float2*)(r2 + 88) = make_float2(rho.x * 5.0f, rho.y * 5.0f);
            *(float2*)(r2 + 90) = make_float2(rho.z * 5.0f, phi.x * 5.0f);
            *(float2*)(r2 + 92) = make_float2(phi.y * 5.0f, phi.z * 5.0f);
        }
    }

    __syncthreads();

    // ---- flat vectorized flush: EPB*OUTC floats = 1504 float4 ----
    {
        float4* go4 = (float4*)(out + (size_t)e0 * OUTC);
        const float4* s4 = (const float4*)(s + S_OUT);
        #pragma unroll
        for (int f = t; f < EPB * OUTC / 4; f += TPB) go4[f] = s4[f];
    }
}

extern "C" void kernel_launch(void* const* d_in, const int* in_sizes, int n_in,
                              void* d_out, int out_size) {
    const float* cfg   = (const float*)d_in[0];
    const float* base  = (const float*)d_in[1];
    const float* tgt   = (const float*)d_in[2];
    const float* dbase = (const float*)d_in[3];
    const float* rest  = (const float*)d_in[4];
    const float* joff  = (const float*)d_in[5];
    const float* jaxis = (const float*)d_in[6];
    const float* jlo   = (const float*)d_in[7];
    const float* jup   = (const float*)d_in[8];
    float* out = (float*)d_out;

    const int smem_bytes = S_TOTAL * sizeof(float);   // 28320
    cudaFuncSetAttribute(ik_residual_kernel,
                         cudaFuncAttributeMaxDynamicSharedMemorySize, smem_bytes);

    int B = in_sizes[0] / NJ;     // 65536
    int nblocks = B / EPB;        // 1024

    ik_residual_kernel<<<nblocks, TPB, smem_bytes>>>(cfg, base, tgt, dbase, rest,
                                                     joff, jaxis, jlo, jup, out);
}

// round 12
// speedup vs baseline: 1.0152x; 1.0152x over previous
#include <cuda_runtime.h>

#define NJ   32
#define TPB  128
#define EPB  (TPB / 2)     // 64 elements per block, 2 threads each
#define OUTC 94

// ---- dynamic smem float offsets ----
#define S_OUT   0                       // EPB*OUTC = 6016 floats (also cfg-stage scratch)
#define S_BASE  (EPB * OUTC)            // 6016  (EPB x 8, padded)
#define S_TGT   (S_BASE + EPB * 8)      // 6528  (4 x 8, padded)
#define S_DB    (S_TGT + 32)            // 6560  (8)
#define S_REC   (S_DB + 8)              // 6568  (32 x 16 joint records)
#define S_TOTAL (S_REC + 512)           // 7080 floats = 28320 B

#define CFG_PAD 36                      // padded cfg row stride in staging scratch

struct Q { float x, y, z, w; };
struct V { float x, y, z; };

__device__ __forceinline__ V vcross(V a, V b) {
    return {a.y * b.z - a.z * b.y,
            a.z * b.x - a.x * b.z,
            a.x * b.y - a.y * b.x};
}

__device__ __forceinline__ V qrot(Q q, V t) {
    V v{q.x, q.y, q.z};
    V u = vcross(v, t);
    u.x = fmaf(q.w, t.x, u.x);
    u.y = fmaf(q.w, t.y, u.y);
    u.z = fmaf(q.w, t.z, u.z);
    V c = vcross(v, u);
    return {fmaf(2.0f, c.x, t.x), fmaf(2.0f, c.y, t.y), fmaf(2.0f, c.z, t.z)};
}

__device__ __forceinline__ Q qmul(Q a, Q b) {
    Q r;
    r.w = a.w * b.w - a.x * b.x - a.y * b.y - a.z * b.z;
    r.x = a.w * b.x + b.w * a.x + a.y * b.z - a.z * b.y;
    r.y = a.w * b.y + b.w * a.y + a.z * b.x - a.x * b.z;
    r.z = a.w * b.z + b.w * a.z + a.x * b.y - a.y * b.x;
    return r;
}

// (t1,q1) <- (t1,q1) o (t2,q2)
__device__ __forceinline__ void se3_acc(V& t1, Q& q1, V t2, Q q2) {
    V r = qrot(q1, t2);
    t1.x += r.x; t1.y += r.y; t1.z += r.z;
    q1 = qmul(q1, q2);
}

// out = (t1,q1) o (t2,q2)
__device__ __forceinline__ void se3_comp(V t1, Q q1, V t2, Q q2, V& to, Q& qo) {
    V r = qrot(q1, t2);
    to.x = t1.x + r.x; to.y = t1.y + r.y; to.z = t1.z + r.z;
    qo = qmul(q1, q2);
}

// atan2(y,x), y >= 0, x >= 0, not both zero
__device__ __forceinline__ float atan2pos(float y, float x) {
    float mn = fminf(y, x), mx = fmaxf(y, x);
    float r  = __fdividef(mn, mx);
    float r2 = r * r;
    float p = fmaf(r2, -0.0117212f,  0.05265332f);
    p = fmaf(r2, p, -0.11643287f);
    p = fmaf(r2, p,  0.19354346f);
    p = fmaf(r2, p, -0.33262347f);
    p = fmaf(r2, p,  0.99997726f);
    float th = r * p;
    return (y > x) ? (1.57079632679489662f - th) : th;
}

// se3_log for unit quaternion (trig-free tail)
__device__ __forceinline__ void se3_log(V t, Q q, V& rho, V& phi) {
    float sgn = (q.w < 0.0f) ? -1.0f : 1.0f;
    float qx = q.x * sgn, qy = q.y * sgn, qz = q.z * sgn, qw = q.w * sgn;
    float nv2 = qx * qx + qy * qy + qz * qz;
    float nv  = sqrtf(fmaxf(nv2, 1e-14f));
    float angle = 2.0f * atan2pos(nv, qw);
    float wsafe = (fabsf(qw) > 1e-8f) ? qw : 1.0f;
    float scale = (nv < 1e-6f) ? __fdividef(2.0f, wsafe) : __fdividef(angle, nv);
    phi = {qx * scale, qy * scale, qz * scale};

    float th2 = angle * angle;
    float abig = __fdividef(1.0f - 0.5f * scale * qw, th2);
    float a = (angle < 1e-4f) ? (1.0f / 12.0f + th2 * (1.0f / 720.0f)) : abig;

    V pt  = vcross(phi, t);
    V ppt = vcross(phi, pt);
    rho = {t.x - 0.5f * pt.x + a * ppt.x,
           t.y - 0.5f * pt.y + a * ppt.y,
           t.z - 0.5f * pt.z + a * ppt.z};
}

// log( inv(target) o actual ); target padded to 8 floats: [t(3),pad | q(4)]
__device__ __forceinline__ void pose_err_log(const float* tp, V at, Q aq,
                                             V& rho, V& phi) {
    float4 a = *(const float4*)tp;
    float4 b = *(const float4*)(tp + 4);
    Q qi{-b.x, -b.y, -b.z, b.w};
    V d{at.x - a.x, at.y - a.y, at.z - a.z};
    V pe = qrot(qi, d);
    Q qe = qmul(qi, aq);
    se3_log(pe, qe, rho, phi);
}

// one leaf: M = ch*oq + sh*P, T = ot; also writes limit/rest residuals
__device__ __forceinline__ void leaf(const float4* REC, int j, float thj,
                                     float* row, V& T, Q& M) {
    const float4* R = REC + j * 4;
    float4 a0 = R[0];     // ot, rest
    float4 a1 = R[1];     // oq
    float4 a2 = R[2];     // P
    float4 a3 = R[3];     // up, lo
    float lim = fmaxf(thj - a3.x, 0.0f) + fminf(thj - a3.y, 0.0f);
    row[24 + j] = lim * 10.0f;
    row[56 + j] = (thj - a0.w) * 0.1f;

    float sh, ch;
    __sincosf(0.5f * thj, &sh, &ch);
    M.x = fmaf(sh, a2.x, ch * a1.x);
    M.y = fmaf(sh, a2.y, ch * a1.y);
    M.z = fmaf(sh, a2.z, ch * a1.z);
    M.w = fmaf(sh, a2.w, ch * a1.w);
    T.x = a0.x; T.y = a0.y; T.z = a0.z;
}

// DUAL interleaved 8-joint tree products:
//   SA = X_{j0}   o ... o X_{j0+7}
//   SB = X_{j0+8} o ... o X_{j0+15}
// Every leaf/compose alternates between the two independent trees -> 2x ILP.
__device__ __forceinline__ void prod8x2(const float4* REC, int j0, const float* th,
                                        float* row,
                                        V& SAt, Q& SAq, V& SBt, Q& SBq) {
    V ta, tb, ta2, tb2; Q qa, qb, qa2, qb2;

    // group 1: (X0 o X1) per tree
    leaf(REC, j0 + 0, th[0], row, SAt, SAq);
    leaf(REC, j0 + 8, th[8], row, SBt, SBq);
    leaf(REC, j0 + 1, th[1], row, ta, qa);
    leaf(REC, j0 + 9, th[9], row, tb, qb);
    se3_acc(SAt, SAq, ta, qa);
    se3_acc(SBt, SBq, tb, qb);

    // group 2: (X2 o X3), fold into S
    leaf(REC, j0 + 2,  th[2],  row, ta,  qa);
    leaf(REC, j0 + 10, th[10], row, tb,  qb);
    leaf(REC, j0 + 3,  th[3],  row, ta2, qa2);
    leaf(REC, j0 + 11, th[11], row, tb2, qb2);
    se3_acc(ta, qa, ta2, qa2);
    se3_acc(tb, qb, tb2, qb2);
    se3_acc(SAt, SAq, ta, qa);
    se3_acc(SBt, SBq, tb, qb);

    // group 3: C = (X4 o X5)
    leaf(REC, j0 + 4,  th[4],  row, ta,  qa);
    leaf(REC, j0 + 12, th[12], row, tb,  qb);
    leaf(REC, j0 + 5,  th[5],  row, ta2, qa2);
    leaf(REC, j0 + 13, th[13], row, tb2, qb2);
    se3_acc(ta, qa, ta2, qa2);       // CA
    se3_acc(tb, qb, tb2, qb2);       // CB

    // group 4: D = (X6 o X7); C = C o D; S = S o C
    V ta3, tb3; Q qa3, qb3;
    leaf(REC, j0 + 6,  th[6],  row, ta2, qa2);
    leaf(REC, j0 + 14, th[14], row, tb2, qb2);
    leaf(REC, j0 + 7,  th[7],  row, ta3, qa3);
    leaf(REC, j0 + 15, th[15], row, tb3, qb3);
    se3_acc(ta2, qa2, ta3, qa3);     // DA
    se3_acc(tb2, qb2, tb3, qb3);     // DB
    se3_acc(ta, qa, ta2, qa2);       // CA = CA o DA
    se3_acc(tb, qb, tb2, qb2);       // CB = CB o DB
    se3_acc(SAt, SAq, ta, qa);       // SA final
    se3_acc(SBt, SBq, tb, qb);       // SB final
}

__global__ void __launch_bounds__(TPB, 5)
ik_residual_kernel(const float* __restrict__ cfg,
                   const float* __restrict__ base,
                   const float* __restrict__ tgt,
                   const float* __restrict__ dbase,
                   const float* __restrict__ rest,
                   const float* __restrict__ joff,
                   const float* __restrict__ jaxis,
                   const float* __restrict__ jlo,
                   const float* __restrict__ jup,
                   float* __restrict__ out) {
    extern __shared__ __align__(16) float s[];

    const int t    = threadIdx.x;
    const int elem = t >> 1;        // 0..63
    const int seg  = t & 1;         // 0 -> joints 0-15, 1 -> joints 16-31
    const int e0   = blockIdx.x * EPB;

    // ---- stage: base (padded 8), cfg tile (-> S_OUT scratch), records, targets ----
    {
        const float* gb = base + (size_t)e0 * 7;
        #pragma unroll
        for (int i = t; i < EPB * 7; i += TPB) {
            int r = i / 7, c = i - r * 7;
            s[S_BASE + r * 8 + c] = gb[i];
        }

        const float4* gc = (const float4*)(cfg + (size_t)e0 * NJ);
        #pragma unroll
        for (int f = t; f < EPB * (NJ / 4); f += TPB) {
            int r = f >> 3;
            int c = f & 7;
            *(float4*)(s + S_OUT + r * CFG_PAD + c * 4) = __ldg(gc + f);
        }

        if (t < 32) {
            float otx = __ldg(joff + t * 7 + 0), oty = __ldg(joff + t * 7 + 1);
            float otz = __ldg(joff + t * 7 + 2);
            float ox = __ldg(joff + t * 7 + 3), oy = __ldg(joff + t * 7 + 4);
            float oz = __ldg(joff + t * 7 + 5), ow = __ldg(joff + t * 7 + 6);
            float ax = __ldg(jaxis + t * 3 + 0), ay = __ldg(jaxis + t * 3 + 1);
            float az = __ldg(jaxis + t * 3 + 2);
            float4* R = (float4*)(s + S_REC) + t * 4;
            R[0] = make_float4(otx, oty, otz, __ldg(rest + t));
            R[1] = make_float4(ox, oy, oz, ow);
            R[2] = make_float4(ow * ax + oy * az - oz * ay,
                               ow * ay + oz * ax - ox * az,
                               ow * az + ox * ay - oy * ax,
                               -(ox * ax + oy * ay + oz * az));
            R[3] = make_float4(__ldg(jup + t), __ldg(jlo + t), 0.0f, 0.0f);
        }
        if (t < 5) {
            const float* src = (t < 4) ? (tgt + t * 7) : dbase;
            float* dst = s + ((t < 4) ? (S_TGT + t * 8) : S_DB);
            dst[0] = __ldg(src + 0); dst[1] = __ldg(src + 1);
            dst[2] = __ldg(src + 2); dst[3] = 0.0f;
            dst[4] = __ldg(src + 3); dst[5] = __ldg(src + 4);
            dst[6] = __ldg(src + 5); dst[7] = __ldg(src + 6);
        }
    }
    __syncthreads();

    // own half of cfg row (base pose deferred until after the trees)
    float th[16];
    {
        const float4* cr = (const float4*)(s + S_OUT + elem * CFG_PAD + seg * 16);
        #pragma unroll
        for (int i = 0; i < 4; i++) {
            float4 v = cr[i];
            th[4*i+0] = v.x; th[4*i+1] = v.y; th[4*i+2] = v.z; th[4*i+3] = v.w;
        }
    }
    __syncthreads();   // cfg scratch becomes output staging

    float* row = s + S_OUT + elem * OUTC;
    const float4* REC = (const float4*)(s + S_REC);
    const int j0 = seg * 16;

    // ---- dual interleaved 8-joint products ----
    V S1t, S2t; Q S1q, S2q;
    prod8x2(REC, j0, th, row, S1t, S1q, S2t, S2q);

    V Et; Q Eq;
    se3_comp(S1t, S1q, S2t, S2q, Et, Eq);      // E = 16-joint product

    // ---- base pose (loaded late to shorten live range) ----
    V bt; Q bq;
    {
        float4 b1 = *(const float4*)(s + S_BASE + elem * 8);
        float4 b2 = *(const float4*)(s + S_BASE + elem * 8 + 4);
        bt.x = b1.x; bt.y = b1.y; bt.z = b1.z;
        bq.x = b1.w; bq.y = b2.x; bq.z = b2.y; bq.w = b2.z;
    }

    // ---- G = base o E (lane0 of pair: T16) ----
    V Gt; Q Gq;
    se3_comp(bt, bq, Et, Eq, Gt, Gq);

    // broadcast lane0's G (=T16) within the pair
    V Lt; Q Lq;
    Lt.x = __shfl_sync(0xffffffffu, Gt.x, 0, 2);
    Lt.y = __shfl_sync(0xffffffffu, Gt.y, 0, 2);
    Lt.z = __shfl_sync(0xffffffffu, Gt.z, 0, 2);
    Lq.x = __shfl_sync(0xffffffffu, Gq.x, 0, 2);
    Lq.y = __shfl_sync(0xffffffffu, Gq.y, 0, 2);
    Lq.z = __shfl_sync(0xffffffffu, Gq.z, 0, 2);
    Lq.w = __shfl_sync(0xffffffffu, Gq.w, 0, 2);

    // prefix select: seg0 -> base, seg1 -> T16
    V Pt; Q Pq;
    Pt.x = seg ? Lt.x : bt.x;  Pt.y = seg ? Lt.y : bt.y;  Pt.z = seg ? Lt.z : bt.z;
    Pq.x = seg ? Lq.x : bq.x;  Pq.y = seg ? Lq.y : bq.y;
    Pq.z = seg ? Lq.z : bq.z;  Pq.w = seg ? Lq.w : bq.w;

    // U1 = P o S1 (T8 / T24), U2 = P o E (T16 / T32) -- independent
    V U1t, U2t; Q U1q, U2q;
    se3_comp(Pt, Pq, S1t, S1q, U1t, U1q);
    se3_comp(Pt, Pq, Et,  Eq,  U2t, U2q);

    // ---- pose residuals (2 per thread) ----
    {
        V rho, phi;
        int k = seg * 2;
        pose_err_log(s + S_TGT + k * 8, U1t, U1q, rho, phi);
        *(float2*)(row + k * 6 + 0) = make_float2(rho.x, rho.y);
        *(float2*)(row + k * 6 + 2) = make_float2(rho.z, 0.5f * phi.x);
        *(float2*)(row + k * 6 + 4) = make_float2(0.5f * phi.y, 0.5f * phi.z);

        k = seg * 2 + 1;
        pose_err_log(s + S_TGT + k * 8, U2t, U2q, rho, phi);
        *(float2*)(row + k * 6 + 0) = make_float2(rho.x, rho.y);
        *(float2*)(row + k * 6 + 2) = make_float2(rho.z, 0.5f * phi.x);
        *(float2*)(row + k * 6 + 4) = make_float2(0.5f * phi.y, 0.5f * phi.z);
    }

    // ---- base residuals: all 4 warps, lanes 0-15, one element each ----
    {
        const int lane = t & 31;
        const int w    = t >> 5;
        if (lane < 16) {
            const int el = w * 16 + lane;   // 0..63
            float4 b1 = *(const float4*)(s + S_BASE + el * 8);
            float4 b2 = *(const float4*)(s + S_BASE + el * 8 + 4);
            V rho, phi;
            pose_err_log(s + S_DB, V{b1.x, b1.y, b1.z},
                         Q{b1.w, b2.x, b2.y, b2.z}, rho, phi);
            float* r2 = s + S_OUT + el * OUTC;
            *(float2*)(r2 + 88) = make_float2(rho.x * 5.0f, rho.y * 5.0f);
            *(float2*)(r2 + 90) = make_float2(rho.z * 5.0f, phi.x * 5.0f);
            *(float2*)(r2 + 92) = make_float2(phi.y * 5.0f, phi.z * 5.0f);
        }
    }

    __syncthreads();

    // ---- flat vectorized flush: EPB*OUTC floats = 1504 float4 ----
    {
        float4* go4 = (float4*)(out + (size_t)e0 * OUTC);
        const float4* s4 = (const float4*)(s + S_OUT);
        #pragma unroll
        for (int f = t; f < EPB * OUTC / 4; f += TPB) go4[f] = s4[f];
    }
}

extern "C" void kernel_launch(void* const* d_in, const int* in_sizes, int n_in,
                              void* d_out, int out_size) {
    const float* cfg   = (const float*)d_in[0];
    const float* base  = (const float*)d_in[1];
    const float* tgt   = (const float*)d_in[2];
    const float* dbase = (const float*)d_in[3];
    const float* rest  = (const float*)d_in[4];
    const float* joff  = (const float*)d_in[5];
    const float* jaxis = (const float*)d_in[6];
    const float* jlo   = (const float*)d_in[7];
    const float* jup   = (const float*)d_in[8];
    float* out = (float*)d_out;

    const int smem_bytes = S_TOTAL * sizeof(float);   // 28320
    cudaFuncSetAttribute(ik_residual_kernel,
                         cudaFuncAttributeMaxDynamicSharedMemorySize, smem_bytes);

    int B = in_sizes[0] / NJ;     // 65536
    int nblocks = B / EPB;        // 1024

    ik_residual_kernel<<<nblocks, TPB, smem_bytes>>>(cfg, base, tgt, dbase, rest,
                                                     joff, jaxis, jlo, jup, out);
}

// round 13
// speedup vs baseline: 1.1335x; 1.1165x over previous
#include <cuda_runtime.h>

#define NJ   32
#define TPB  64
#define OUTC 94

typedef unsigned long long u64;

// ---- dynamic smem float offsets ----
#define S_OUT   0                       // 64*94 = 6016 (flush staging; cfg scratch early)
#define S_BASE  6016                    // 64 x 8
#define S_DB    6528                    // 8 (scalar default-base, padded)
#define S_LIM   6536                    // 32 x 4 (up, lo, rest, pad)
#define S_TGT2  6664                    // 2 pairs x 10 u64 = 40 floats
#define S_PREC  6704                    // 16 leaf-pairs x 12 u64 = 384 floats
#define S_TOTAL 7088                    // 28352 B

#define CFG_PAD 36

// ---- packed f32x2 primitives ----
__device__ __forceinline__ u64 f2pack(float lo, float hi) {
    u64 r;
    asm("mov.b64 %0, {%1, %2};" : "=l"(r)
        : "r"(__float_as_uint(lo)), "r"(__float_as_uint(hi)));
    return r;
}
__device__ __forceinline__ void f2unp(u64 a, float& lo, float& hi) {
    unsigned l, h;
    asm("mov.b64 {%0, %1}, %2;" : "=r"(l), "=r"(h) : "l"(a));
    lo = __uint_as_float(l); hi = __uint_as_float(h);
}
__device__ __forceinline__ u64 f2mul(u64 a, u64 b) {
    u64 r; asm("mul.rn.f32x2 %0, %1, %2;" : "=l"(r) : "l"(a), "l"(b)); return r;
}
__device__ __forceinline__ u64 f2add(u64 a, u64 b) {
    u64 r; asm("add.rn.f32x2 %0, %1, %2;" : "=l"(r) : "l"(a), "l"(b)); return r;
}
__device__ __forceinline__ u64 f2fma(u64 a, u64 b, u64 c) {
    u64 r; asm("fma.rn.f32x2 %0, %1, %2, %3;" : "=l"(r) : "l"(a), "l"(b), "l"(c)); return r;
}

#define C_NEG1  0xBF800000BF800000ULL
#define C_TWO   0x4000000040000000ULL
#define C_NHALF 0xBF000000BF000000ULL

struct Q { float x, y, z, w; };
struct V { float x, y, z; };
struct V2 { u64 x, y, z; };
struct Q2 { u64 x, y, z, w; };

// ================= scalar helpers =================
__device__ __forceinline__ V vcross(V a, V b) {
    return {a.y * b.z - a.z * b.y,
            a.z * b.x - a.x * b.z,
            a.x * b.y - a.y * b.x};
}
__device__ __forceinline__ V qrot(Q q, V t) {
    V v{q.x, q.y, q.z};
    V u = vcross(v, t);
    u.x = fmaf(q.w, t.x, u.x);
    u.y = fmaf(q.w, t.y, u.y);
    u.z = fmaf(q.w, t.z, u.z);
    V c = vcross(v, u);
    return {fmaf(2.0f, c.x, t.x), fmaf(2.0f, c.y, t.y), fmaf(2.0f, c.z, t.z)};
}
__device__ __forceinline__ Q qmul(Q a, Q b) {
    Q r;
    r.w = a.w * b.w - a.x * b.x - a.y * b.y - a.z * b.z;
    r.x = a.w * b.x + b.w * a.x + a.y * b.z - a.z * b.y;
    r.y = a.w * b.y + b.w * a.y + a.z * b.x - a.x * b.z;
    r.z = a.w * b.z + b.w * a.z + a.x * b.y - a.y * b.x;
    return r;
}
__device__ __forceinline__ void se3_comp(V t1, Q q1, V t2, Q q2, V& to, Q& qo) {
    V r = qrot(q1, t2);
    to.x = t1.x + r.x; to.y = t1.y + r.y; to.z = t1.z + r.z;
    qo = qmul(q1, q2);
}
__device__ __forceinline__ float atan2pos(float y, float x) {
    float mn = fminf(y, x), mx = fmaxf(y, x);
    float r  = __fdividef(mn, mx);
    float r2 = r * r;
    float p = fmaf(r2, -0.0117212f,  0.05265332f);
    p = fmaf(r2, p, -0.11643287f);
    p = fmaf(r2, p,  0.19354346f);
    p = fmaf(r2, p, -0.33262347f);
    p = fmaf(r2, p,  0.99997726f);
    float th = r * p;
    return (y > x) ? (1.57079632679489662f - th) : th;
}
__device__ __forceinline__ void se3_log(V t, Q q, V& rho, V& phi) {
    float sgn = (q.w < 0.0f) ? -1.0f : 1.0f;
    float qx = q.x * sgn, qy = q.y * sgn, qz = q.z * sgn, qw = q.w * sgn;
    float nv2 = qx * qx + qy * qy + qz * qz;
    float nv  = sqrtf(fmaxf(nv2, 1e-14f));
    float angle = 2.0f * atan2pos(nv, qw);
    float wsafe = (fabsf(qw) > 1e-8f) ? qw : 1.0f;
    float scale = (nv < 1e-6f) ? __fdividef(2.0f, wsafe) : __fdividef(angle, nv);
    phi = {qx * scale, qy * scale, qz * scale};
    float th2 = angle * angle;
    float abig = __fdividef(1.0f - 0.5f * scale * qw, th2);
    float a = (angle < 1e-4f) ? (1.0f / 12.0f + th2 * (1.0f / 720.0f)) : abig;
    V pt  = vcross(phi, t);
    V ppt = vcross(phi, pt);
    rho = {t.x - 0.5f * pt.x + a * ppt.x,
           t.y - 0.5f * pt.y + a * ppt.y,
           t.z - 0.5f * pt.z + a * ppt.z};
}
// scalar pose_err vs padded-8 target [t(3),pad | q(4)]
__device__ __forceinline__ void pose_err_log(const float* tp, V at, Q aq,
                                             V& rho, V& phi) {
    float4 a = *(const float4*)tp;
    float4 b = *(const float4*)(tp + 4);
    Q qi{-b.x, -b.y, -b.z, b.w};
    V d{at.x - a.x, at.y - a.y, at.z - a.z};
    V pe = qrot(qi, d);
    Q qe = qmul(qi, aq);
    se3_log(pe, qe, rho, phi);
}

// ================= packed helpers (validated in R4) =================
__device__ __forceinline__ void log_scalars(float nv2, float qw,
                                            float& scale, float& a) {
    float nv  = sqrtf(fmaxf(nv2, 1e-14f));
    float qwc = fabsf(qw);
    float angle = 2.0f * atan2pos(nv, qwc);
    float wsafe = (qwc > 1e-8f) ? qwc : 1.0f;
    scale = (nv < 1e-6f) ? __fdividef(2.0f, wsafe) : __fdividef(angle, nv);
    float th2  = angle * angle;
    float abig = __fdividef(1.0f - 0.5f * scale * qwc, th2);
    a = (angle < 1e-4f) ? (1.0f / 12.0f + th2 * (1.0f / 720.0f)) : abig;
}

__device__ __forceinline__ void se3_log2(V2 t, Q2 q, V2& rho, V2& phi) {
    const u64 NEG1 = C_NEG1, NHALF = C_NHALF;
    float qwA, qwB; f2unp(q.w, qwA, qwB);
    u64 sg = f2pack(qwA < 0.0f ? -1.0f : 1.0f, qwB < 0.0f ? -1.0f : 1.0f);
    u64 qx = f2mul(q.x, sg), qy = f2mul(q.y, sg), qz = f2mul(q.z, sg);
    u64 nv2 = f2fma(qx, qx, f2fma(qy, qy, f2mul(qz, qz)));
    float n2A, n2B; f2unp(nv2, n2A, n2B);
    float scA, aA, scB, aB;
    log_scalars(n2A, qwA, scA, aA);
    log_scalars(n2B, qwB, scB, aB);
    u64 sc = f2pack(scA, scB), a2 = f2pack(aA, aB);
    phi.x = f2mul(qx, sc); phi.y = f2mul(qy, sc); phi.z = f2mul(qz, sc);
    u64 nx = f2mul(phi.x, NEG1), ny = f2mul(phi.y, NEG1), nz = f2mul(phi.z, NEG1);
    u64 ptx = f2fma(phi.y, t.z, f2mul(nz, t.y));
    u64 pty = f2fma(phi.z, t.x, f2mul(nx, t.z));
    u64 ptz = f2fma(phi.x, t.y, f2mul(ny, t.x));
    u64 px = f2fma(phi.y, ptz, f2mul(nz, pty));
    u64 py = f2fma(phi.z, ptx, f2mul(nx, ptz));
    u64 pz = f2fma(phi.x, pty, f2mul(ny, ptx));
    rho.x = f2fma(a2, px, f2fma(NHALF, ptx, t.x));
    rho.y = f2fma(a2, py, f2fma(NHALF, pty, t.y));
    rho.z = f2fma(a2, pz, f2fma(NHALF, ptz, t.z));
}

// packed pose err; tp = 10 u64: [-t(3), qi(4), +q.xyz(3)]
__device__ __forceinline__ void pose_err2(const u64* tp, V2 at, Q2 aq,
                                          V2& rho, V2& phi) {
    const u64 TWO = C_TWO;
    V2 d{f2add(at.x, tp[0]), f2add(at.y, tp[1]), f2add(at.z, tp[2])};
    u64 qix = tp[3], qiy = tp[4], qiz = tp[5], qiw = tp[6];
    u64 nx = tp[7], ny = tp[8], nz = tp[9];
    u64 ux = f2fma(qiy, d.z, f2mul(nz, d.y)); ux = f2fma(qiw, d.x, ux);
    u64 uy = f2fma(qiz, d.x, f2mul(nx, d.z)); uy = f2fma(qiw, d.y, uy);
    u64 uz = f2fma(qix, d.y, f2mul(ny, d.x)); uz = f2fma(qiw, d.z, uz);
    u64 cx = f2fma(qiy, uz, f2mul(nz, uy));
    u64 cy = f2fma(qiz, ux, f2mul(nx, uz));
    u64 cz = f2fma(qix, uy, f2mul(ny, ux));
    V2 pe{f2fma(TWO, cx, d.x), f2fma(TWO, cy, d.y), f2fma(TWO, cz, d.z)};
    Q2 qe;
    qe.w = f2fma(nx, aq.x, f2fma(ny, aq.y, f2fma(nz, aq.z, f2mul(qiw, aq.w))));
    qe.x = f2fma(qiy, aq.z, f2fma(nz, aq.y, f2fma(qiw, aq.x, f2mul(qix, aq.w))));
    qe.y = f2fma(qiz, aq.x, f2fma(nx, aq.z, f2fma(qiw, aq.y, f2mul(qiy, aq.w))));
    qe.z = f2fma(qix, aq.y, f2fma(ny, aq.x, f2fma(qiw, aq.z, f2mul(qiz, aq.w))));
    se3_log2(pe, qe, rho, phi);
}

// packed SE3 accumulate: (t1,q1) <- (t1,q1) o (t2,q2)
__device__ __forceinline__ void se3_acc2(V2& t1, Q2& q1, V2 t2, Q2 q2) {
    const u64 NEG1 = C_NEG1, TWO = C_TWO;
    u64 nx = f2mul(q1.x, NEG1), ny = f2mul(q1.y, NEG1), nz = f2mul(q1.z, NEG1);
    u64 ux = f2fma(q1.y, t2.z, f2mul(nz, t2.y)); ux = f2fma(q1.w, t2.x, ux);
    u64 uy = f2fma(q1.z, t2.x, f2mul(nx, t2.z)); uy = f2fma(q1.w, t2.y, uy);
    u64 uz = f2fma(q1.x, t2.y, f2mul(ny, t2.x)); uz = f2fma(q1.w, t2.z, uz);
    u64 cx = f2fma(q1.y, uz, f2mul(nz, uy));
    u64 cy = f2fma(q1.z, ux, f2mul(nx, uz));
    u64 cz = f2fma(q1.x, uy, f2mul(ny, ux));
    t1.x = f2fma(TWO, cx, f2add(t1.x, t2.x));
    t1.y = f2fma(TWO, cy, f2add(t1.y, t2.y));
    t1.z = f2fma(TWO, cz, f2add(t1.z, t2.z));
    u64 w = f2fma(nx, q2.x, f2fma(ny, q2.y, f2fma(nz, q2.z, f2mul(q1.w, q2.w))));
    u64 x = f2fma(q1.y, q2.z, f2fma(nz, q2.y, f2fma(q1.w, q2.x, f2mul(q1.x, q2.w))));
    u64 y = f2fma(q1.z, q2.x, f2fma(nx, q2.z, f2fma(q1.w, q2.y, f2mul(q1.y, q2.w))));
    u64 z = f2fma(q1.x, q2.y, f2fma(ny, q2.x, f2fma(q1.w, q2.z, f2mul(q1.z, q2.w))));
    q1.x = x; q1.y = y; q1.z = z; q1.w = w;
}

// packed leaf lp: record = 6 ulonglong2: {otx,oty}{otz,oqx}{oqy,oqz}{oqw,Px}{Py,Pz}{Pw,pad}
__device__ __forceinline__ void leaf2(const ulonglong2* PR, int lp,
                                      float thA, float thB, V2& T, Q2& M) {
    const ulonglong2* r = PR + lp * 6;
    ulonglong2 r0 = r[0], r1 = r[1], r2 = r[2], r3 = r[3], r4 = r[4], r5 = r[5];
    float shA, chA, shB, chB;
    __sincosf(0.5f * thA, &shA, &chA);
    __sincosf(0.5f * thB, &shB, &chB);
    u64 sh = f2pack(shA, shB), ch = f2pack(chA, chB);
    T.x = r0.x; T.y = r0.y; T.z = r1.x;
    M.x = f2fma(sh, r3.y, f2mul(ch, r1.y));
    M.y = f2fma(sh, r4.x, f2mul(ch, r2.x));
    M.z = f2fma(sh, r4.y, f2mul(ch, r2.y));
    M.w = f2fma(sh, r5.x, f2mul(ch, r3.x));
}

__global__ void __launch_bounds__(TPB)
ik_residual_kernel(const float* __restrict__ cfg,
                   const float* __restrict__ base,
                   const float* __restrict__ tgt,
                   const float* __restrict__ dbase,
                   const float* __restrict__ rest,
                   const float* __restrict__ joff,
                   const float* __restrict__ jaxis,
                   const float* __restrict__ jlo,
                   const float* __restrict__ jup,
                   float* __restrict__ out) {
    extern __shared__ __align__(16) float s[];

    const int t  = threadIdx.x;
    const int b0 = blockIdx.x * TPB;

    // ---- stage: base (pad 8), cfg tile (-> S_OUT scratch), LIM, packed records/targets ----
    {
        const float* gb = base + (size_t)b0 * 7;
        #pragma unroll
        for (int i = t; i < TPB * 7; i += TPB) {
            int r = i / 7, c = i - r * 7;
            s[S_BASE + r * 8 + c] = gb[i];
        }
        const float4* gc = (const float4*)(cfg + (size_t)b0 * NJ);
        #pragma unroll
        for (int f = t; f < TPB * (NJ / 4); f += TPB) {
            int r = f >> 3, c = f & 7;
            *(float4*)(s + S_OUT + r * CFG_PAD + c * 4) = __ldg(gc + f);
        }
        if (t < 32) {   // limit/rest records
            s[S_LIM + t * 4 + 0] = __ldg(jup + t);
            s[S_LIM + t * 4 + 1] = __ldg(jlo + t);
            s[S_LIM + t * 4 + 2] = __ldg(rest + t);
            s[S_LIM + t * 4 + 3] = 0.0f;
        }
        if (t < 16) {   // packed leaf-pair records: pair (jA, jB) = (sp*16+i, sp*16+8+i)
            int sp = t >> 3, i = t & 7;
            int jA = sp * 16 + i, jB = jA + 8;
            float2* d = (float2*)(s + S_PREC) + t * 12;
            float vA[10], vB[10];   // ot(3), oq(4), P(3->4)
            #pragma unroll
            for (int u = 0; u < 2; u++) {
                int j = u ? jB : jA;
                float otx = __ldg(joff + j * 7 + 0), oty = __ldg(joff + j * 7 + 1);
                float otz = __ldg(joff + j * 7 + 2);
                float ox = __ldg(joff + j * 7 + 3), oy = __ldg(joff + j * 7 + 4);
                float oz = __ldg(joff + j * 7 + 5), ow = __ldg(joff + j * 7 + 6);
                float ax = __ldg(jaxis + j * 3 + 0), ay = __ldg(jaxis + j * 3 + 1);
                float az = __ldg(jaxis + j * 3 + 2);
                float* v = u ? vB : vA;
                v[0] = otx; v[1] = oty; v[2] = otz;
                v[3] = ox; v[4] = oy; v[5] = oz; v[6] = ow;
                v[7] = ow * ax + oy * az - oz * ay;
                v[8] = ow * ay + oz * ax - ox * az;
                v[9] = ow * az + ox * ay - oy * ax;
            }
            float PwA = -(vA[3] * __ldg(jaxis + jA * 3 + 0) + vA[4] * __ldg(jaxis + jA * 3 + 1) + vA[5] * __ldg(jaxis + jA * 3 + 2));
            float PwB = -(vB[3] * __ldg(jaxis + jB * 3 + 0) + vB[4] * __ldg(jaxis + jB * 3 + 1) + vB[5] * __ldg(jaxis + jB * 3 + 2));
            #pragma unroll
            for (int k = 0; k < 10; k++) d[k] = make_float2(vA[k], vB[k]);
            d[10] = make_float2(PwA, PwB);
            d[11] = make_float2(0.0f, 0.0f);
        }
        if (t >= 48 && t < 50) {   // packed target pairs (tgt 2p, 2p+1)
            int p = t - 48;
            const float* A = tgt + (2 * p) * 7;
            const float* Bp = tgt + (2 * p + 1) * 7;
            float2* d = (float2*)(s + S_TGT2) + p * 10;
            d[0] = make_float2(-__ldg(A + 0), -__ldg(Bp + 0));
            d[1] = make_float2(-__ldg(A + 1), -__ldg(Bp + 1));
            d[2] = make_float2(-__ldg(A + 2), -__ldg(Bp + 2));
            d[3] = make_float2(-__ldg(A + 3), -__ldg(Bp + 3));
            d[4] = make_float2(-__ldg(A + 4), -__ldg(Bp + 4));
            d[5] = make_float2(-__ldg(A + 5), -__ldg(Bp + 5));
            d[6] = make_float2( __ldg(A + 6),  __ldg(Bp + 6));
            d[7] = make_float2( __ldg(A + 3),  __ldg(Bp + 3));
            d[8] = make_float2( __ldg(A + 4),  __ldg(Bp + 4));
            d[9] = make_float2( __ldg(A + 5),  __ldg(Bp + 5));
        }
        if (t == 50) {   // scalar default base, padded 8
            s[S_DB + 0] = __ldg(dbase + 0); s[S_DB + 1] = __ldg(dbase + 1);
            s[S_DB + 2] = __ldg(dbase + 2); s[S_DB + 3] = 0.0f;
            s[S_DB + 4] = __ldg(dbase + 3); s[S_DB + 5] = __ldg(dbase + 4);
            s[S_DB + 6] = __ldg(dbase + 5); s[S_DB + 7] = __ldg(dbase + 6);
        }
    }
    __syncthreads();

    // own base pose + cfg row
    float bp[7];
    {
        float4 b1 = *(const float4*)(s + S_BASE + t * 8);
        float4 b2 = *(const float4*)(s + S_BASE + t * 8 + 4);
        bp[0] = b1.x; bp[1] = b1.y; bp[2] = b1.z; bp[3] = b1.w;
        bp[4] = b2.x; bp[5] = b2.y; bp[6] = b2.z;
    }
    float th[NJ];
    {
        const float4* cr = (const float4*)(s + S_OUT + t * CFG_PAD);
        #pragma unroll
        for (int i = 0; i < NJ / 4; i++) {
            float4 v = cr[i];
            th[4*i+0] = v.x; th[4*i+1] = v.y; th[4*i+2] = v.z; th[4*i+3] = v.w;
        }
    }
    __syncthreads();   // cfg scratch becomes output staging

    float* row = s + S_OUT + t * OUTC;
    const ulonglong2* PR = (const ulonglong2*)(s + S_PREC);

    // ---- limit / rest residuals ----
    #pragma unroll
    for (int j = 0; j < NJ; j += 2) {
        float4 A  = *(const float4*)(s + S_LIM + j * 4);
        float4 Bv = *(const float4*)(s + S_LIM + (j + 1) * 4);
        float limA = fmaxf(th[j] - A.x, 0.0f)     + fminf(th[j] - A.y, 0.0f);
        float limB = fmaxf(th[j+1] - Bv.x, 0.0f)  + fminf(th[j+1] - Bv.y, 0.0f);
        *(float2*)(row + 24 + j) = make_float2(limA * 10.0f, limB * 10.0f);
        *(float2*)(row + 56 + j) = make_float2((th[j] - A.z) * 0.1f,
                                               (th[j+1] - Bv.z) * 0.1f);
    }

    // ---- two packed tree streams: stream sp covers segs (2sp, 2sp+1) ----
    V S0, S1, S2, S3; Q q0, q1, q2, q3;
    #pragma unroll
    for (int sp = 0; sp < 2; sp++) {
        const int b8 = sp * 8, j16 = sp * 16;
        V2 St, ta, tb, tc; Q2 Sq, qa, qb, qc;
        leaf2(PR, b8 + 0, th[j16 + 0], th[j16 + 8],  St, Sq);
        leaf2(PR, b8 + 1, th[j16 + 1], th[j16 + 9],  ta, qa);
        se3_acc2(St, Sq, ta, qa);
        leaf2(PR, b8 + 2, th[j16 + 2], th[j16 + 10], ta, qa);
        leaf2(PR, b8 + 3, th[j16 + 3], th[j16 + 11], tb, qb);
        se3_acc2(ta, qa, tb, qb);
        se3_acc2(St, Sq, ta, qa);
        leaf2(PR, b8 + 4, th[j16 + 4], th[j16 + 12], tc, qc);
        leaf2(PR, b8 + 5, th[j16 + 5], th[j16 + 13], ta, qa);
        se3_acc2(tc, qc, ta, qa);
        leaf2(PR, b8 + 6, th[j16 + 6], th[j16 + 14], ta, qa);
        leaf2(PR, b8 + 7, th[j16 + 7], th[j16 + 15], tb, qb);
        se3_acc2(ta, qa, tb, qb);
        se3_acc2(tc, qc, ta, qa);
        se3_acc2(St, Sq, tc, qc);

        // unpack: lo -> seg 2sp product, hi -> seg 2sp+1 product
        V* lo_t = sp ? &S2 : &S0;  Q* lo_q = sp ? &q2 : &q0;
        V* hi_t = sp ? &S3 : &S1;  Q* hi_q = sp ? &q3 : &q1;
        f2unp(St.x, lo_t->x, hi_t->x);
        f2unp(St.y, lo_t->y, hi_t->y);
        f2unp(St.z, lo_t->z, hi_t->z);
        f2unp(Sq.x, lo_q->x, hi_q->x);
        f2unp(Sq.y, lo_q->y, hi_q->y);
        f2unp(Sq.z, lo_q->z, hi_q->z);
        f2unp(Sq.w, lo_q->w, hi_q->w);
    }

    // ---- scalar prefix chain: T8, T16, T24, T32 ----
    V bt{bp[0], bp[1], bp[2]};
    Q bq{bp[3], bp[4], bp[5], bp[6]};
    V T8t, T16t, T24t, T32t; Q T8q, T16q, T24q, T32q;
    se3_comp(bt, bq, S0, q0, T8t, T8q);
    se3_comp(T8t, T8q, S1, q1, T16t, T16q);
    se3_comp(T16t, T16q, S2, q2, T24t, T24q);
    se3_comp(T24t, T24q, S3, q3, T32t, T32q);

    // ---- packed pose residuals: (T8,T16) vs (tgt0,tgt1), (T24,T32) vs (tgt2,tgt3) ----
    #pragma unroll
    for (int p = 0; p < 2; p++) {
        V2 at; Q2 aq;
        if (p == 0) {
            at.x = f2pack(T8t.x, T16t.x); at.y = f2pack(T8t.y, T16t.y); at.z = f2pack(T8t.z, T16t.z);
            aq.x = f2pack(T8q.x, T16q.x); aq.y = f2pack(T8q.y, T16q.y);
            aq.z = f2pack(T8q.z, T16q.z); aq.w = f2pack(T8q.w, T16q.w);
        } else {
            at.x = f2pack(T24t.x, T32t.x); at.y = f2pack(T24t.y, T32t.y); at.z = f2pack(T24t.z, T32t.z);
            aq.x = f2pack(T24q.x, T32q.x); aq.y = f2pack(T24q.y, T32q.y);
            aq.z = f2pack(T24q.z, T32q.z); aq.w = f2pack(T24q.w, T32q.w);
        }
        V2 rho, phi;
        pose_err2((const u64*)(s + S_TGT2) + p * 10, at, aq, rho, phi);
        const int kA = p * 2, kB = p * 2 + 1;
        float a0, b0, a1, b1, a2, b2, a3, b3, a4, b4, a5, b5;
        f2unp(rho.x, a0, b0); f2unp(rho.y, a1, b1); f2unp(rho.z, a2, b2);
        f2unp(phi.x, a3, b3); f2unp(phi.y, a4, b4); f2unp(phi.z, a5, b5);
        *(float2*)(row + kA * 6 + 0) = make_float2(a0, a1);
        *(float2*)(row + kA * 6 + 2) = make_float2(a2, 0.5f * a3);
        *(float2*)(row + kA * 6 + 4) = make_float2(0.5f * a4, 0.5f * a5);
        *(float2*)(row + kB * 6 + 0) = make_float2(b0, b1);
        *(float2*)(row + kB * 6 + 2) = make_float2(b2, 0.5f * b3);
        *(float2*)(row + kB * 6 + 4) = make_float2(0.5f * b4, 0.5f * b5);
    }

    // ---- base residual (scalar) ----
    {
        V rho, phi;
        pose_err_log(s + S_DB, bt, bq, rho, phi);
        *(float2*)(row + 88) = make_float2(rho.x * 5.0f, rho.y * 5.0f);
        *(float2*)(row + 90) = make_float2(rho.z * 5.0f, phi.x * 5.0f);
        *(float2*)(row + 92) = make_float2(phi.y * 5.0f, phi.z * 5.0f);
    }

    __syncthreads();

    // ---- flat vectorized flush ----
    {
        float4* go4 = (float4*)(out + (size_t)b0 * OUTC);
        const float4* s4 = (const float4*)(s + S_OUT);
        for (int f = t; f < TPB * OUTC / 4; f += TPB) go4[f] = s4[f];
    }
}

extern "C" void kernel_launch(void* const* d_in, const int* in_sizes, int n_in,
                              void* d_out, int out_size) {
    const float* cfg   = (const float*)d_in[0];
    const float* base  = (const float*)d_in[1];
    const float* tgt   = (const float*)d_in[2];
    const float* dbase = (const float*)d_in[3];
    const float* rest  = (const float*)d_in[4];
    const float* joff  = (const float*)d_in[5];
    const float* jaxis = (const float*)d_in[6];
    const float* jlo   = (const float*)d_in[7];
    const float* jup   = (const float*)d_in[8];
    float* out = (float*)d_out;

    const int smem_bytes = S_TOTAL * sizeof(float);   // 28352
    cudaFuncSetAttribute(ik_residual_kernel,
                         cudaFuncAttributeMaxDynamicSharedMemorySize, smem_bytes);

    int B = in_sizes[0] / NJ;     // 65536
    int nblocks = B / TPB;        // 1024

    ik_residual_kernel<<<nblocks, TPB, smem_bytes>>>(cfg, base, tgt, dbase, rest,
                                                     joff, jaxis, jlo, jup, out);
}

// round 14
// speedup vs baseline: 1.1555x; 1.0194x over previous
#include <cuda_runtime.h>

#define NJ   32
#define TPB  128
#define OUTC 94

typedef unsigned long long u64;

// ---- dynamic smem float offsets ----
#define S_OUT   0                       // TPB*94 = 12032 (flush staging; cfg scratch early)
#define S_BASE  12032                   // TPB x 8
#define S_DB    13056                   // 8 (scalar default-base, padded)
#define S_LIM   13064                   // 32 x 4 (up, lo, rest, pad)
#define S_TGT2  13192                   // 2 pairs x 10 u64 = 40 floats
#define S_PREC  13232                   // 16 leaf-pairs x 12 u64 = 384 floats (16B aligned)
#define S_TOTAL 13616                   // 54464 B

#define CFG_PAD 36

// ---- packed f32x2 primitives ----
__device__ __forceinline__ u64 f2pack(float lo, float hi) {
    u64 r;
    asm("mov.b64 %0, {%1, %2};" : "=l"(r)
        : "r"(__float_as_uint(lo)), "r"(__float_as_uint(hi)));
    return r;
}
__device__ __forceinline__ void f2unp(u64 a, float& lo, float& hi) {
    unsigned l, h;
    asm("mov.b64 {%0, %1}, %2;" : "=r"(l), "=r"(h) : "l"(a));
    lo = __uint_as_float(l); hi = __uint_as_float(h);
}
__device__ __forceinline__ u64 f2mul(u64 a, u64 b) {
    u64 r; asm("mul.rn.f32x2 %0, %1, %2;" : "=l"(r) : "l"(a), "l"(b)); return r;
}
__device__ __forceinline__ u64 f2add(u64 a, u64 b) {
    u64 r; asm("add.rn.f32x2 %0, %1, %2;" : "=l"(r) : "l"(a), "l"(b)); return r;
}
__device__ __forceinline__ u64 f2fma(u64 a, u64 b, u64 c) {
    u64 r; asm("fma.rn.f32x2 %0, %1, %2, %3;" : "=l"(r) : "l"(a), "l"(b), "l"(c)); return r;
}

#define C_NEG1  0xBF800000BF800000ULL
#define C_TWO   0x4000000040000000ULL
#define C_NHALF 0xBF000000BF000000ULL

struct Q { float x, y, z, w; };
struct V { float x, y, z; };
struct V2 { u64 x, y, z; };
struct Q2 { u64 x, y, z, w; };

// ================= scalar helpers =================
__device__ __forceinline__ V vcross(V a, V b) {
    return {a.y * b.z - a.z * b.y,
            a.z * b.x - a.x * b.z,
            a.x * b.y - a.y * b.x};
}
__device__ __forceinline__ V qrot(Q q, V t) {
    V v{q.x, q.y, q.z};
    V u = vcross(v, t);
    u.x = fmaf(q.w, t.x, u.x);
    u.y = fmaf(q.w, t.y, u.y);
    u.z = fmaf(q.w, t.z, u.z);
    V c = vcross(v, u);
    return {fmaf(2.0f, c.x, t.x), fmaf(2.0f, c.y, t.y), fmaf(2.0f, c.z, t.z)};
}
__device__ __forceinline__ Q qmul(Q a, Q b) {
    Q r;
    r.w = a.w * b.w - a.x * b.x - a.y * b.y - a.z * b.z;
    r.x = a.w * b.x + b.w * a.x + a.y * b.z - a.z * b.y;
    r.y = a.w * b.y + b.w * a.y + a.z * b.x - a.x * b.z;
    r.z = a.w * b.z + b.w * a.z + a.x * b.y - a.y * b.x;
    return r;
}
__device__ __forceinline__ void se3_comp(V t1, Q q1, V t2, Q q2, V& to, Q& qo) {
    V r = qrot(q1, t2);
    to.x = t1.x + r.x; to.y = t1.y + r.y; to.z = t1.z + r.z;
    qo = qmul(q1, q2);
}
__device__ __forceinline__ float atan2pos(float y, float x) {
    float mn = fminf(y, x), mx = fmaxf(y, x);
    float r  = __fdividef(mn, mx);
    float r2 = r * r;
    float p = fmaf(r2, -0.0117212f,  0.05265332f);
    p = fmaf(r2, p, -0.11643287f);
    p = fmaf(r2, p,  0.19354346f);
    p = fmaf(r2, p, -0.33262347f);
    p = fmaf(r2, p,  0.99997726f);
    float th = r * p;
    return (y > x) ? (1.57079632679489662f - th) : th;
}
__device__ __forceinline__ void se3_log(V t, Q q, V& rho, V& phi) {
    float sgn = (q.w < 0.0f) ? -1.0f : 1.0f;
    float qx = q.x * sgn, qy = q.y * sgn, qz = q.z * sgn, qw = q.w * sgn;
    float nv2 = qx * qx + qy * qy + qz * qz;
    float nv  = sqrtf(fmaxf(nv2, 1e-14f));
    float angle = 2.0f * atan2pos(nv, qw);
    float wsafe = (fabsf(qw) > 1e-8f) ? qw : 1.0f;
    float scale = (nv < 1e-6f) ? __fdividef(2.0f, wsafe) : __fdividef(angle, nv);
    phi = {qx * scale, qy * scale, qz * scale};
    float th2 = angle * angle;
    float abig = __fdividef(1.0f - 0.5f * scale * qw, th2);
    float a = (angle < 1e-4f) ? (1.0f / 12.0f + th2 * (1.0f / 720.0f)) : abig;
    V pt  = vcross(phi, t);
    V ppt = vcross(phi, pt);
    rho = {t.x - 0.5f * pt.x + a * ppt.x,
           t.y - 0.5f * pt.y + a * ppt.y,
           t.z - 0.5f * pt.z + a * ppt.z};
}
// scalar pose_err vs padded-8 target [t(3),pad | q(4)]
__device__ __forceinline__ void pose_err_log(const float* tp, V at, Q aq,
                                             V& rho, V& phi) {
    float4 a = *(const float4*)tp;
    float4 b = *(const float4*)(tp + 4);
    Q qi{-b.x, -b.y, -b.z, b.w};
    V d{at.x - a.x, at.y - a.y, at.z - a.z};
    V pe = qrot(qi, d);
    Q qe = qmul(qi, aq);
    se3_log(pe, qe, rho, phi);
}

// ================= packed helpers (validated in R4/R13) =================
__device__ __forceinline__ void log_scalars(float nv2, float qw,
                                            float& scale, float& a) {
    float nv  = sqrtf(fmaxf(nv2, 1e-14f));
    float qwc = fabsf(qw);
    float angle = 2.0f * atan2pos(nv, qwc);
    float wsafe = (qwc > 1e-8f) ? qwc : 1.0f;
    scale = (nv < 1e-6f) ? __fdividef(2.0f, wsafe) : __fdividef(angle, nv);
    float th2  = angle * angle;
    float abig = __fdividef(1.0f - 0.5f * scale * qwc, th2);
    a = (angle < 1e-4f) ? (1.0f / 12.0f + th2 * (1.0f / 720.0f)) : abig;
}

__device__ __forceinline__ void se3_log2(V2 t, Q2 q, V2& rho, V2& phi) {
    const u64 NEG1 = C_NEG1, NHALF = C_NHALF;
    float qwA, qwB; f2unp(q.w, qwA, qwB);
    u64 sg = f2pack(qwA < 0.0f ? -1.0f : 1.0f, qwB < 0.0f ? -1.0f : 1.0f);
    u64 qx = f2mul(q.x, sg), qy = f2mul(q.y, sg), qz = f2mul(q.z, sg);
    u64 nv2 = f2fma(qx, qx, f2fma(qy, qy, f2mul(qz, qz)));
    float n2A, n2B; f2unp(nv2, n2A, n2B);
    float scA, aA, scB, aB;
    log_scalars(n2A, qwA, scA, aA);
    log_scalars(n2B, qwB, scB, aB);
    u64 sc = f2pack(scA, scB), a2 = f2pack(aA, aB);
    phi.x = f2mul(qx, sc); phi.y = f2mul(qy, sc); phi.z = f2mul(qz, sc);
    u64 nx = f2mul(phi.x, NEG1), ny = f2mul(phi.y, NEG1), nz = f2mul(phi.z, NEG1);
    u64 ptx = f2fma(phi.y, t.z, f2mul(nz, t.y));
    u64 pty = f2fma(phi.z, t.x, f2mul(nx, t.z));
    u64 ptz = f2fma(phi.x, t.y, f2mul(ny, t.x));
    u64 px = f2fma(phi.y, ptz, f2mul(nz, pty));
    u64 py = f2fma(phi.z, ptx, f2mul(nx, ptz));
    u64 pz = f2fma(phi.x, pty, f2mul(ny, ptx));
    rho.x = f2fma(a2, px, f2fma(NHALF, ptx, t.x));
    rho.y = f2fma(a2, py, f2fma(NHALF, pty, t.y));
    rho.z = f2fma(a2, pz, f2fma(NHALF, ptz, t.z));
}

// packed pose err; tp = 10 u64: [-t(3), qi(4), +q.xyz(3)]
__device__ __forceinline__ void pose_err2(const u64* tp, V2 at, Q2 aq,
                                          V2& rho, V2& phi) {
    const u64 TWO = C_TWO;
    V2 d{f2add(at.x, tp[0]), f2add(at.y, tp[1]), f2add(at.z, tp[2])};
    u64 qix = tp[3], qiy = tp[4], qiz = tp[5], qiw = tp[6];
    u64 nx = tp[7], ny = tp[8], nz = tp[9];
    u64 ux = f2fma(qiy, d.z, f2mul(nz, d.y)); ux = f2fma(qiw, d.x, ux);
    u64 uy = f2fma(qiz, d.x, f2mul(nx, d.z)); uy = f2fma(qiw, d.y, uy);
    u64 uz = f2fma(qix, d.y, f2mul(ny, d.x)); uz = f2fma(qiw, d.z, uz);
    u64 cx = f2fma(qiy, uz, f2mul(nz, uy));
    u64 cy = f2fma(qiz, ux, f2mul(nx, uz));
    u64 cz = f2fma(qix, uy, f2mul(ny, ux));
    V2 pe{f2fma(TWO, cx, d.x), f2fma(TWO, cy, d.y), f2fma(TWO, cz, d.z)};
    Q2 qe;
    qe.w = f2fma(nx, aq.x, f2fma(ny, aq.y, f2fma(nz, aq.z, f2mul(qiw, aq.w))));
    qe.x = f2fma(qiy, aq.z, f2fma(nz, aq.y, f2fma(qiw, aq.x, f2mul(qix, aq.w))));
    qe.y = f2fma(qiz, aq.x, f2fma(nx, aq.z, f2fma(qiw, aq.y, f2mul(qiy, aq.w))));
    qe.z = f2fma(qix, aq.y, f2fma(ny, aq.x, f2fma(qiw, aq.z, f2mul(qiz, aq.w))));
    se3_log2(pe, qe, rho, phi);
}

// packed SE3 accumulate: (t1,q1) <- (t1,q1) o (t2,q2)
__device__ __forceinline__ void se3_acc2(V2& t1, Q2& q1, V2 t2, Q2 q2) {
    const u64 NEG1 = C_NEG1, TWO = C_TWO;
    u64 nx = f2mul(q1.x, NEG1), ny = f2mul(q1.y, NEG1), nz = f2mul(q1.z, NEG1);
    u64 ux = f2fma(q1.y, t2.z, f2mul(nz, t2.y)); ux = f2fma(q1.w, t2.x, ux);
    u64 uy = f2fma(q1.z, t2.x, f2mul(nx, t2.z)); uy = f2fma(q1.w, t2.y, uy);
    u64 uz = f2fma(q1.x, t2.y, f2mul(ny, t2.x)); uz = f2fma(q1.w, t2.z, uz);
    u64 cx = f2fma(q1.y, uz, f2mul(nz, uy));
    u64 cy = f2fma(q1.z, ux, f2mul(nx, uz));
    u64 cz = f2fma(q1.x, uy, f2mul(ny, ux));
    t1.x = f2fma(TWO, cx, f2add(t1.x, t2.x));
    t1.y = f2fma(TWO, cy, f2add(t1.y, t2.y));
    t1.z = f2fma(TWO, cz, f2add(t1.z, t2.z));
    u64 w = f2fma(nx, q2.x, f2fma(ny, q2.y, f2fma(nz, q2.z, f2mul(q1.w, q2.w))));
    u64 x = f2fma(q1.y, q2.z, f2fma(nz, q2.y, f2fma(q1.w, q2.x, f2mul(q1.x, q2.w))));
    u64 y = f2fma(q1.z, q2.x, f2fma(nx, q2.z, f2fma(q1.w, q2.y, f2mul(q1.y, q2.w))));
    u64 z = f2fma(q1.x, q2.y, f2fma(ny, q2.x, f2fma(q1.w, q2.z, f2mul(q1.z, q2.w))));
    q1.x = x; q1.y = y; q1.z = z; q1.w = w;
}

// packed leaf lp: record = 6 ulonglong2: {otx,oty}{otz,oqx}{oqy,oqz}{oqw,Px}{Py,Pz}{Pw,pad}
__device__ __forceinline__ void leaf2(const ulonglong2* PR, int lp,
                                      float thA, float thB, V2& T, Q2& M) {
    const ulonglong2* r = PR + lp * 6;
    ulonglong2 r0 = r[0], r1 = r[1], r2 = r[2], r3 = r[3], r4 = r[4], r5 = r[5];
    float shA, chA, shB, chB;
    __sincosf(0.5f * thA, &shA, &chA);
    __sincosf(0.5f * thB, &shB, &chB);
    u64 sh = f2pack(shA, shB), ch = f2pack(chA, chB);
    T.x = r0.x; T.y = r0.y; T.z = r1.x;
    M.x = f2fma(sh, r3.y, f2mul(ch, r1.y));
    M.y = f2fma(sh, r4.x, f2mul(ch, r2.x));
    M.z = f2fma(sh, r4.y, f2mul(ch, r2.y));
    M.w = f2fma(sh, r5.x, f2mul(ch, r3.x));
}

__global__ void __launch_bounds__(TPB)
ik_residual_kernel(const float* __restrict__ cfg,
                   const float* __restrict__ base,
                   const float* __restrict__ tgt,
                   const float* __restrict__ dbase,
                   const float* __restrict__ rest,
                   const float* __restrict__ joff,
                   const float* __restrict__ jaxis,
                   const float* __restrict__ jlo,
                   const float* __restrict__ jup,
                   float* __restrict__ out) {
    extern __shared__ __align__(16) float s[];

    const int t  = threadIdx.x;
    const int b0 = blockIdx.x * TPB;

    // ---- stage: base (pad 8), cfg tile (-> S_OUT scratch), LIM, packed records/targets ----
    {
        const float* gb = base + (size_t)b0 * 7;
        #pragma unroll
        for (int i = t; i < TPB * 7; i += TPB) {
            int r = i / 7, c = i - r * 7;
            s[S_BASE + r * 8 + c] = gb[i];
        }
        const float4* gc = (const float4*)(cfg + (size_t)b0 * NJ);
        #pragma unroll
        for (int f = t; f < TPB * (NJ / 4); f += TPB) {
            int r = f >> 3, c = f & 7;
            *(float4*)(s + S_OUT + r * CFG_PAD + c * 4) = __ldg(gc + f);
        }
        if (t < 32) {   // limit/rest records
            s[S_LIM + t * 4 + 0] = __ldg(jup + t);
            s[S_LIM + t * 4 + 1] = __ldg(jlo + t);
            s[S_LIM + t * 4 + 2] = __ldg(rest + t);
            s[S_LIM + t * 4 + 3] = 0.0f;
        }
        if (t < 16) {   // packed leaf-pair records: pair (jA, jB) = (sp*16+i, sp*16+8+i)
            int sp = t >> 3, i = t & 7;
            int jA = sp * 16 + i, jB = jA + 8;
            float2* d = (float2*)(s + S_PREC) + t * 12;
            float vA[10], vB[10];   // ot(3), oq(4), P(3)
            #pragma unroll
            for (int u = 0; u < 2; u++) {
                int j = u ? jB : jA;
                float otx = __ldg(joff + j * 7 + 0), oty = __ldg(joff + j * 7 + 1);
                float otz = __ldg(joff + j * 7 + 2);
                float ox = __ldg(joff + j * 7 + 3), oy = __ldg(joff + j * 7 + 4);
                float oz = __ldg(joff + j * 7 + 5), ow = __ldg(joff + j * 7 + 6);
                float ax = __ldg(jaxis + j * 3 + 0), ay = __ldg(jaxis + j * 3 + 1);
                float az = __ldg(jaxis + j * 3 + 2);
                float* v = u ? vB : vA;
                v[0] = otx; v[1] = oty; v[2] = otz;
                v[3] = ox; v[4] = oy; v[5] = oz; v[6] = ow;
                v[7] = ow * ax + oy * az - oz * ay;
                v[8] = ow * ay + oz * ax - ox * az;
                v[9] = ow * az + ox * ay - oy * ax;
            }
            float PwA = -(vA[3] * __ldg(jaxis + jA * 3 + 0) + vA[4] * __ldg(jaxis + jA * 3 + 1) + vA[5] * __ldg(jaxis + jA * 3 + 2));
            float PwB = -(vB[3] * __ldg(jaxis + jB * 3 + 0) + vB[4] * __ldg(jaxis + jB * 3 + 1) + vB[5] * __ldg(jaxis + jB * 3 + 2));
            #pragma unroll
            for (int k = 0; k < 10; k++) d[k] = make_float2(vA[k], vB[k]);
            d[10] = make_float2(PwA, PwB);
            d[11] = make_float2(0.0f, 0.0f);
        }
        if (t >= 48 && t < 50) {   // packed target pairs (tgt 2p, 2p+1)
            int p = t - 48;
            const float* A = tgt + (2 * p) * 7;
            const float* Bp = tgt + (2 * p + 1) * 7;
            float2* d = (float2*)(s + S_TGT2) + p * 10;
            d[0] = make_float2(-__ldg(A + 0), -__ldg(Bp + 0));
            d[1] = make_float2(-__ldg(A + 1), -__ldg(Bp + 1));
            d[2] = make_float2(-__ldg(A + 2), -__ldg(Bp + 2));
            d[3] = make_float2(-__ldg(A + 3), -__ldg(Bp + 3));
            d[4] = make_float2(-__ldg(A + 4), -__ldg(Bp + 4));
            d[5] = make_float2(-__ldg(A + 5), -__ldg(Bp + 5));
            d[6] = make_float2( __ldg(A + 6),  __ldg(Bp + 6));
            d[7] = make_float2( __ldg(A + 3),  __ldg(Bp + 3));
            d[8] = make_float2( __ldg(A + 4),  __ldg(Bp + 4));
            d[9] = make_float2( __ldg(A + 5),  __ldg(Bp + 5));
        }
        if (t == 50) {   // scalar default base, padded 8
            s[S_DB + 0] = __ldg(dbase + 0); s[S_DB + 1] = __ldg(dbase + 1);
            s[S_DB + 2] = __ldg(dbase + 2); s[S_DB + 3] = 0.0f;
            s[S_DB + 4] = __ldg(dbase + 3); s[S_DB + 5] = __ldg(dbase + 4);
            s[S_DB + 6] = __ldg(dbase + 5); s[S_DB + 7] = __ldg(dbase + 6);
        }
    }
    __syncthreads();

    // own base pose + cfg row
    float bp[7];
    {
        float4 b1 = *(const float4*)(s + S_BASE + t * 8);
        float4 b2 = *(const float4*)(s + S_BASE + t * 8 + 4);
        bp[0] = b1.x; bp[1] = b1.y; bp[2] = b1.z; bp[3] = b1.w;
        bp[4] = b2.x; bp[5] = b2.y; bp[6] = b2.z;
    }
    float th[NJ];
    {
        const float4* cr = (const float4*)(s + S_OUT + t * CFG_PAD);
        #pragma unroll
        for (int i = 0; i < NJ / 4; i++) {
            float4 v = cr[i];
            th[4*i+0] = v.x; th[4*i+1] = v.y; th[4*i+2] = v.z; th[4*i+3] = v.w;
        }
    }
    __syncthreads();   // cfg scratch becomes output staging

    float* row = s + S_OUT + t * OUTC;
    const ulonglong2* PR = (const ulonglong2*)(s + S_PREC);

    // ---- limit / rest residuals ----
    #pragma unroll
    for (int j = 0; j < NJ; j += 2) {
        float4 A  = *(const float4*)(s + S_LIM + j * 4);
        float4 Bv = *(const float4*)(s + S_LIM + (j + 1) * 4);
        float limA = fmaxf(th[j] - A.x, 0.0f)     + fminf(th[j] - A.y, 0.0f);
        float limB = fmaxf(th[j+1] - Bv.x, 0.0f)  + fminf(th[j+1] - Bv.y, 0.0f);
        *(float2*)(row + 24 + j) = make_float2(limA * 10.0f, limB * 10.0f);
        *(float2*)(row + 56 + j) = make_float2((th[j] - A.z) * 0.1f,
                                               (th[j+1] - Bv.z) * 0.1f);
    }

    // ---- two packed tree streams: stream sp covers segs (2sp, 2sp+1) ----
    V S0, S1, S2, S3; Q q0, q1, q2, q3;
    #pragma unroll
    for (int sp = 0; sp < 2; sp++) {
        const int b8 = sp * 8, j16 = sp * 16;
        V2 St, ta, tb, tc; Q2 Sq, qa, qb, qc;
        leaf2(PR, b8 + 0, th[j16 + 0], th[j16 + 8],  St, Sq);
        leaf2(PR, b8 + 1, th[j16 + 1], th[j16 + 9],  ta, qa);
        se3_acc2(St, Sq, ta, qa);
        leaf2(PR, b8 + 2, th[j16 + 2], th[j16 + 10], ta, qa);
        leaf2(PR, b8 + 3, th[j16 + 3], th[j16 + 11], tb, qb);
        se3_acc2(ta, qa, tb, qb);
        se3_acc2(St, Sq, ta, qa);
        leaf2(PR, b8 + 4, th[j16 + 4], th[j16 + 12], tc, qc);
        leaf2(PR, b8 + 5, th[j16 + 5], th[j16 + 13], ta, qa);
        se3_acc2(tc, qc, ta, qa);
        leaf2(PR, b8 + 6, th[j16 + 6], th[j16 + 14], ta, qa);
        leaf2(PR, b8 + 7, th[j16 + 7], th[j16 + 15], tb, qb);
        se3_acc2(ta, qa, tb, qb);
        se3_acc2(tc, qc, ta, qa);
        se3_acc2(St, Sq, tc, qc);

        // unpack: lo -> seg 2sp product, hi -> seg 2sp+1 product
        V* lo_t = sp ? &S2 : &S0;  Q* lo_q = sp ? &q2 : &q0;
        V* hi_t = sp ? &S3 : &S1;  Q* hi_q = sp ? &q3 : &q1;
        f2unp(St.x, lo_t->x, hi_t->x);
        f2unp(St.y, lo_t->y, hi_t->y);
        f2unp(St.z, lo_t->z, hi_t->z);
        f2unp(Sq.x, lo_q->x, hi_q->x);
        f2unp(Sq.y, lo_q->y, hi_q->y);
        f2unp(Sq.z, lo_q->z, hi_q->z);
        f2unp(Sq.w, lo_q->w, hi_q->w);
    }

    // ---- scalar prefix chain: T8, T16, T24, T32 ----
    V bt{bp[0], bp[1], bp[2]};
    Q bq{bp[3], bp[4], bp[5], bp[6]};
    V T8t, T16t, T24t, T32t; Q T8q, T16q, T24q, T32q;
    se3_comp(bt, bq, S0, q0, T8t, T8q);
    se3_comp(T8t, T8q, S1, q1, T16t, T16q);
    se3_comp(T16t, T16q, S2, q2, T24t, T24q);
    se3_comp(T24t, T24q, S3, q3, T32t, T32q);

    // ---- packed pose residuals: (T8,T16) vs (tgt0,tgt1), (T24,T32) vs (tgt2,tgt3) ----
    #pragma unroll
    for (int p = 0; p < 2; p++) {
        V2 at; Q2 aq;
        if (p == 0) {
            at.x = f2pack(T8t.x, T16t.x); at.y = f2pack(T8t.y, T16t.y); at.z = f2pack(T8t.z, T16t.z);
            aq.x = f2pack(T8q.x, T16q.x); aq.y = f2pack(T8q.y, T16q.y);
            aq.z = f2pack(T8q.z, T16q.z); aq.w = f2pack(T8q.w, T16q.w);
        } else {
            at.x = f2pack(T24t.x, T32t.x); at.y = f2pack(T24t.y, T32t.y); at.z = f2pack(T24t.z, T32t.z);
            aq.x = f2pack(T24q.x, T32q.x); aq.y = f2pack(T24q.y, T32q.y);
            aq.z = f2pack(T24q.z, T32q.z); aq.w = f2pack(T24q.w, T32q.w);
        }
        V2 rho, phi;
        pose_err2((const u64*)(s + S_TGT2) + p * 10, at, aq, rho, phi);
        const int kA = p * 2, kB = p * 2 + 1;
        float a0, b0, a1, b1, a2, b2, a3, b3, a4, b4, a5, b5;
        f2unp(rho.x, a0, b0); f2unp(rho.y, a1, b1); f2unp(rho.z, a2, b2);
        f2unp(phi.x, a3, b3); f2unp(phi.y, a4, b4); f2unp(phi.z, a5, b5);
        *(float2*)(row + kA * 6 + 0) = make_float2(a0, a1);
        *(float2*)(row + kA * 6 + 2) = make_float2(a2, 0.5f * a3);
        *(float2*)(row + kA * 6 + 4) = make_float2(0.5f * a4, 0.5f * a5);
        *(float2*)(row + kB * 6 + 0) = make_float2(b0, b1);
        *(float2*)(row + kB * 6 + 2) = make_float2(b2, 0.5f * b3);
        *(float2*)(row + kB * 6 + 4) = make_float2(0.5f * b4, 0.5f * b5);
    }

    // ---- base residual (scalar) ----
    {
        V rho, phi;
        pose_err_log(s + S_DB, bt, bq, rho, phi);
        *(float2*)(row + 88) = make_float2(rho.x * 5.0f, rho.y * 5.0f);
        *(float2*)(row + 90) = make_float2(rho.z * 5.0f, phi.x * 5.0f);
        *(float2*)(row + 92) = make_float2(phi.y * 5.0f, phi.z * 5.0f);
    }

    __syncthreads();

    // ---- flat vectorized flush ----
    {
        float4* go4 = (float4*)(out + (size_t)b0 * OUTC);
        const float4* s4 = (const float4*)(s + S_OUT);
        for (int f = t; f < TPB * OUTC / 4; f += TPB) go4[f] = s4[f];
    }
}

extern "C" void kernel_launch(void* const* d_in, const int* in_sizes, int n_in,
                              void* d_out, int out_size) {
    const float* cfg   = (const float*)d_in[0];
    const float* base  = (const float*)d_in[1];
    const float* tgt   = (const float*)d_in[2];
    const float* dbase = (const float*)d_in[3];
    const float* rest  = (const float*)d_in[4];
    const float* joff  = (const float*)d_in[5];
    const float* jaxis = (const float*)d_in[6];
    const float* jlo   = (const float*)d_in[7];
    const float* jup   = (const float*)d_in[8];
    float* out = (float*)d_out;

    const int smem_bytes = S_TOTAL * sizeof(float);   // 54464
    cudaFuncSetAttribute(ik_residual_kernel,
                         cudaFuncAttributeMaxDynamicSharedMemorySize, smem_bytes);

    int B = in_sizes[0] / NJ;     // 65536
    int nblocks = B / TPB;        // 512

    ik_residual_kernel<<<nblocks, TPB, smem_bytes>>>(cfg, base, tgt, dbase, rest,
                                                     joff, jaxis, jlo, jup, out);
}